// round 16
// baseline (speedup 1.0000x reference)
#include <cuda_runtime.h>
#include <cuda_fp16.h>
#include <cstdint>
#include <math.h>

#define BATCH 4
#define SEQ   2048
#define DMODEL 1024
#define NHEADS 16
#define DK    64
#define MTOT  (BATCH*SEQ)      // 8192
#define NEGV  (-1e9f)
#define MW    (SEQ/32)         // 64 mask words per row

// Scratch (alloc-free rule: __device__ globals).
__device__ __half   g_Xh[MTOT * DMODEL];       // x in fp16
__device__ __half   g_Wh[4 * DMODEL * DMODEL]; // Wq,Wk,Wv,Wo in fp16
__device__ __half   g_P [3 * MTOT * DMODEL];   // Q(scaled)|K|V slices
__device__ __half   g_Ch[MTOT * DMODEL];       // ctx in fp16
__device__ uint32_t g_Mb[BATCH * SEQ * MW];    // bit-packed mask (2 MB)

__device__ __forceinline__ uint32_t pack_f16x2(float lo, float hi) {
    uint32_t r;
    asm("cvt.rn.f16x2.f32 %0, %1, %2;" : "=r"(r) : "f"(hi), "f"(lo));
    return r;
}

__device__ __forceinline__ uint32_t sptr(const void* p) {
    return (uint32_t)__cvta_generic_to_shared(p);
}

__device__ __forceinline__ void cp_async16(uint32_t smem, const void* g) {
    asm volatile("cp.async.cg.shared.global [%0], [%1], 16;" :: "r"(smem), "l"(g));
}
#define CP_COMMIT() asm volatile("cp.async.commit_group;")
#define CP_WAIT(N)  asm volatile("cp.async.wait_group %0;" :: "n"(N))

__device__ __forceinline__ void ldsm_x4(uint32_t* r, uint32_t addr) {
    asm volatile("ldmatrix.sync.aligned.m8n8.x4.shared.b16 {%0,%1,%2,%3}, [%4];"
                 : "=r"(r[0]), "=r"(r[1]), "=r"(r[2]), "=r"(r[3]) : "r"(addr));
}

__device__ __forceinline__ void ldsm_x4_t(uint32_t* r, uint32_t addr) {
    asm volatile("ldmatrix.sync.aligned.m8n8.x4.trans.shared.b16 {%0,%1,%2,%3}, [%4];"
                 : "=r"(r[0]), "=r"(r[1]), "=r"(r[2]), "=r"(r[3]) : "r"(addr));
}

__device__ __forceinline__ void mma_f16(float* c, const uint32_t* a, const uint32_t* b) {
    asm volatile(
        "mma.sync.aligned.m16n8k16.row.col.f32.f16.f16.f32 "
        "{%0,%1,%2,%3}, {%4,%5,%6,%7}, {%8,%9}, {%0,%1,%2,%3};"
        : "+f"(c[0]), "+f"(c[1]), "+f"(c[2]), "+f"(c[3])
        : "r"(a[0]), "r"(a[1]), "r"(a[2]), "r"(a[3]), "r"(b[0]), "r"(b[1]));
}

// ---------------------------------------------------------------------------
// fp32 -> fp16 bulk convert
// ---------------------------------------------------------------------------
__global__ __launch_bounds__(256) void cvt_f16(const float* __restrict__ src,
                                               __half* __restrict__ dst, int n4)
{
    int i = blockIdx.x * 256 + threadIdx.x;
    if (i >= n4) return;
    float4 v = *(const float4*)(src + (size_t)i * 4);
    uint2 o;
    o.x = pack_f16x2(v.x, v.y);
    o.y = pack_f16x2(v.z, v.w);
    *(uint2*)(dst + (size_t)i * 4) = o;
}

// ---------------------------------------------------------------------------
// Bit-pack the int32 mask
// ---------------------------------------------------------------------------
__global__ __launch_bounds__(256) void pack_mask(const int* __restrict__ mask,
                                                 uint32_t* __restrict__ mb)
{
    int w    = blockIdx.x * 8 + (threadIdx.x >> 5);
    int lane = threadIdx.x & 31;
    int v    = mask[(size_t)w * 32 + lane];
    uint32_t bits = __ballot_sync(0xffffffffu, v != 0);
    if (lane == 0) mb[w] = bits;
}

// ---------------------------------------------------------------------------
// fp16 GEMM, 3-stage cp.async pipeline, z-batched weights.
// CTA tile 256x128, K-tile 64, 256 threads (8 warps: 4M x 2N, warp 64x64).
// For z = blockIdx.z: Y_z = A @ W_z + bias_z ; z==0 scaled by s0.
// ---------------------------------------------------------------------------
#define TBM 256
#define TBN 128
#define TBK 64
#define AP  72
#define BP  136
#define NKT (DMODEL / TBK)   // 16
#define STG 3
#define ASZH (TBM * AP)      // 18432 halfs
#define BSZH (TBK * BP)      // 8704 halfs
#define ASZB (ASZH * 2)      // 36864 B
#define BSZB (BSZH * 2)      // 17408 B
#define GSMEM (STG * (ASZB + BSZB))  // 162816 B

template <typename OutT>
__global__ __launch_bounds__(256, 1) void gemm_f16_t(
    const __half* __restrict__ A, const __half* __restrict__ Wbase,
    const float* __restrict__ b0, const float* __restrict__ b1,
    const float* __restrict__ b2, OutT* __restrict__ Ybase, float s0)
{
    extern __shared__ __half dsm[];
    __half* Asm = dsm;
    __half* Bsm = dsm + STG * ASZH;

    const int tid  = threadIdx.x;
    const int wid  = tid >> 5;
    const int lane = tid & 31;
    const int gid  = lane >> 2;
    const int ctid = lane & 3;
    const int wm   = wid & 3;     // 4 warps along M, 64 rows each
    const int wn   = wid >> 2;    // 2 warps along N, 64 cols each

    const int z  = blockIdx.z;
    const __half* W = Wbase + (size_t)z * DMODEL * DMODEL;
    OutT* Y = Ybase + (size_t)z * MTOT * DMODEL;
    const float* bias = (z == 0) ? b0 : (z == 1) ? b1 : b2;
    const float oscale = (z == 0) ? s0 : 1.0f;

    const int bm = blockIdx.y * TBM;
    const int bn = blockIdx.x * TBN;

    float acc[4][8][4];
#pragma unroll
    for (int i = 0; i < 4; i++)
#pragma unroll
        for (int j = 0; j < 8; j++)
#pragma unroll
            for (int t = 0; t < 4; t++) acc[i][j][t] = 0.f;

    // per-thread cp.async coordinates: A 2048 uint4 (8/thr), B 1024 uint4 (4/thr)
    int ar[8], ac[8], br[4], bc[4];
    uint32_t asw[8], bsw[4];
#pragma unroll
    for (int i = 0; i < 8; i++) {
        int f = i * 256 + tid;
        ar[i] = f >> 3;  ac[i] = (f & 7) * 8;
        asw[i] = sptr(&Asm[ar[i] * AP + ac[i]]);
    }
#pragma unroll
    for (int i = 0; i < 4; i++) {
        int f = i * 256 + tid;
        br[i] = f >> 4;  bc[i] = (f & 15) * 8;
        bsw[i] = sptr(&Bsm[br[i] * BP + bc[i]]);
    }

    const uint32_t a_base0 = sptr(&Asm[(wm * 64 + (lane & 15)) * AP + (lane >> 4) * 8]);
    const uint32_t b_base0 = sptr(&Bsm[((lane & 7) + (lane >> 3) * 8) * BP + wn * 64]);

    // prefetch stages 0,1 (tiles 0,1)
#pragma unroll
    for (int s = 0; s < 2; s++) {
        const int k0 = s * TBK;
#pragma unroll
        for (int i = 0; i < 8; i++)
            cp_async16(asw[i] + s * ASZB, A + (size_t)(bm + ar[i]) * DMODEL + k0 + ac[i]);
#pragma unroll
        for (int i = 0; i < 4; i++)
            cp_async16(bsw[i] + s * BSZB, W + (size_t)(k0 + br[i]) * DMODEL + bn + bc[i]);
        CP_COMMIT();
    }

    int cur = 0;
    for (int kt = 0; kt < NKT; kt++) {
        if (kt + 2 < NKT) {
            const int nst = (cur == 0) ? 2 : cur - 1;   // (cur+2)%3
            const int k0  = (kt + 2) * TBK;
#pragma unroll
            for (int i = 0; i < 8; i++)
                cp_async16(asw[i] + nst * ASZB, A + (size_t)(bm + ar[i]) * DMODEL + k0 + ac[i]);
#pragma unroll
            for (int i = 0; i < 4; i++)
                cp_async16(bsw[i] + nst * BSZB, W + (size_t)(k0 + br[i]) * DMODEL + bn + bc[i]);
            CP_COMMIT();
            CP_WAIT(2);
        } else if (kt + 1 < NKT) {
            CP_WAIT(1);
        } else {
            CP_WAIT(0);
        }
        __syncthreads();

        const uint32_t a_base = a_base0 + cur * ASZB;
        const uint32_t b_base = b_base0 + cur * BSZB;
#pragma unroll
        for (int kh = 0; kh < 2; kh++) {
            uint32_t a[4][2][4];
#pragma unroll
            for (int mt = 0; mt < 4; mt++)
#pragma unroll
                for (int ks = 0; ks < 2; ks++)
                    ldsm_x4(a[mt][ks], a_base + mt * 16 * AP * 2 + (kh * 2 + ks) * 32);
#pragma unroll
            for (int nt = 0; nt < 8; nt++) {
                uint32_t bb[4];
                ldsm_x4_t(bb, b_base + kh * 32 * BP * 2 + nt * 16);
#pragma unroll
                for (int mt = 0; mt < 4; mt++) {
                    mma_f16(acc[mt][nt], a[mt][0], bb);
                    mma_f16(acc[mt][nt], a[mt][1], bb + 2);
                }
            }
        }
        __syncthreads();
        cur = (cur == 2) ? 0 : cur + 1;
    }

#pragma unroll
    for (int nt = 0; nt < 8; nt++) {
        int c = bn + wn * 64 + nt * 8 + ctid * 2;
        float bb0 = __ldg(bias + c);
        float bb1 = __ldg(bias + c + 1);
#pragma unroll
        for (int mt = 0; mt < 4; mt++) {
            int r0 = bm + wm * 64 + mt * 16 + gid;
            float v00 = (acc[mt][nt][0] + bb0) * oscale;
            float v01 = (acc[mt][nt][1] + bb1) * oscale;
            float v10 = (acc[mt][nt][2] + bb0) * oscale;
            float v11 = (acc[mt][nt][3] + bb1) * oscale;
            if constexpr (sizeof(OutT) == 4) {
                float2 p0 = make_float2(v00, v01);
                float2 p1 = make_float2(v10, v11);
                *(float2*)((float*)Y + (size_t)r0 * DMODEL + c)       = p0;
                *(float2*)((float*)Y + (size_t)(r0 + 8) * DMODEL + c) = p1;
            } else {
                uint32_t p0 = pack_f16x2(v00, v01);
                uint32_t p1 = pack_f16x2(v10, v11);
                *(uint32_t*)((__half*)Y + (size_t)r0 * DMODEL + c)       = p0;
                *(uint32_t*)((__half*)Y + (size_t)(r0 + 8) * DMODEL + c) = p1;
            }
        }
    }
}

// ---------------------------------------------------------------------------
// Flash attention (R13, unchanged): fp16 mma.sync, 3-stage cp.async,
// ldmatrix fragments, bit-packed mask. 256 threads; 128 q/block; key tile 64.
// ---------------------------------------------------------------------------
#define FKT 64
#define KVP 72
#define NFT (SEQ / FKT)        // 32
#define KVSZB (FKT * KVP * 2)  // 9216 B per stage

__global__ __launch_bounds__(256, 2) void flash_f16(
    const __half* __restrict__ Qh, const __half* __restrict__ Kh,
    const __half* __restrict__ Vh, const uint32_t* __restrict__ mbits,
    __half* __restrict__ Ctx)
{
    __shared__ __align__(16) __half Ks[STG][FKT * KVP];
    __shared__ __align__(16) __half Vs[STG][FKT * KVP];

    const int tid  = threadIdx.x;
    const int w    = tid >> 5;
    const int lane = tid & 31;
    const int gid  = lane >> 2;
    const int ctid = lane & 3;

    const int h  = blockIdx.y;
    const int b  = blockIdx.z;
    const int qb = blockIdx.x * 128 + w * 16;

    uint32_t qa[4][4];
    {
        const __half* q0 = Qh + (size_t)(b * SEQ + qb + gid    ) * DMODEL + h * DK;
        const __half* q1 = Qh + (size_t)(b * SEQ + qb + gid + 8) * DMODEL + h * DK;
#pragma unroll
        for (int t = 0; t < 4; t++) {
            qa[t][0] = *(const uint32_t*)(q0 + 16 * t + 2 * ctid);
            qa[t][1] = *(const uint32_t*)(q1 + 16 * t + 2 * ctid);
            qa[t][2] = *(const uint32_t*)(q0 + 16 * t + 2 * ctid + 8);
            qa[t][3] = *(const uint32_t*)(q1 + 16 * t + 2 * ctid + 8);
        }
    }

    float m0 = -INFINITY, m1 = -INFINITY, l0 = 0.f, l1 = 0.f;
    float o[8][4];
#pragma unroll
    for (int nd = 0; nd < 8; nd++)
#pragma unroll
        for (int t = 0; t < 4; t++) o[nd][t] = 0.f;

    const uint32_t* mb0 = mbits + ((size_t)(b * SEQ) + qb + gid) * MW;
    const uint32_t* mb1 = mb0 + 8 * MW;

    int kr[2], kc[2];
    uint32_t ksw[2], vsw[2];
#pragma unroll
    for (int i = 0; i < 2; i++) {
        int f = i * 256 + tid;
        kr[i] = f >> 3;  kc[i] = (f & 7) * 8;
        ksw[i] = sptr(&Ks[0][kr[i] * KVP + kc[i]]);
        vsw[i] = sptr(&Vs[0][kr[i] * KVP + kc[i]]);
    }

    const uint32_t ks_base0 = sptr(&Ks[0][(lane & 7) * KVP + (lane >> 3) * 8]);
    const uint32_t vs_base0 = sptr(&Vs[0][((lane & 7) + (lane >> 3) * 8) * KVP]);

#pragma unroll
    for (int s = 0; s < 2; s++) {
#pragma unroll
        for (int i = 0; i < 2; i++) {
            size_t ga = (size_t)(b * SEQ + s * FKT + kr[i]) * DMODEL + h * DK + kc[i];
            cp_async16(ksw[i] + s * KVSZB, Kh + ga);
            cp_async16(vsw[i] + s * KVSZB, Vh + ga);
        }
        CP_COMMIT();
    }

    int cur = 0;
    for (int ft = 0; ft < NFT; ft++) {
        const int kt = ft * FKT;
        if (ft + 2 < NFT) {
            const int nst = (cur == 0) ? 2 : cur - 1;
#pragma unroll
            for (int i = 0; i < 2; i++) {
                size_t ga = (size_t)(b * SEQ + kt + 2 * FKT + kr[i]) * DMODEL + h * DK + kc[i];
                cp_async16(ksw[i] + nst * KVSZB, Kh + ga);
                cp_async16(vsw[i] + nst * KVSZB, Vh + ga);
            }
            CP_COMMIT();
            CP_WAIT(2);
        } else if (ft + 1 < NFT) {
            CP_WAIT(1);
        } else {
            CP_WAIT(0);
        }
        __syncthreads();

        uint2 w0 = *(const uint2*)(mb0 + (kt >> 5));
        uint2 w1 = *(const uint2*)(mb1 + (kt >> 5));

        const uint32_t ks_base = ks_base0 + cur * KVSZB;
        const uint32_t vs_base = vs_base0 + cur * KVSZB;

        float sc[8][4];
#pragma unroll
        for (int nt = 0; nt < 8; nt++) {
#pragma unroll
            for (int t4 = 0; t4 < 4; t4++) sc[nt][t4] = 0.f;
            uint32_t bk[8];
            uint32_t base = ks_base + nt * 8 * KVP * 2;
            ldsm_x4(bk,     base);
            ldsm_x4(bk + 4, base + 64);
            mma_f16(sc[nt], qa[0], bk);
            mma_f16(sc[nt], qa[1], bk + 2);
            mma_f16(sc[nt], qa[2], bk + 4);
            mma_f16(sc[nt], qa[3], bk + 6);
        }

#pragma unroll
        for (int nt = 0; nt < 8; nt++) {
            int kl = nt * 8 + 2 * ctid;
            uint32_t wr0 = (kl & 32) ? w0.y : w0.x;
            uint32_t wr1 = (kl & 32) ? w1.y : w1.x;
            int sh = kl & 31;
            if ((wr0 >> sh) & 1)       sc[nt][0] = NEGV;
            if ((wr0 >> (sh + 1)) & 1) sc[nt][1] = NEGV;
            if ((wr1 >> sh) & 1)       sc[nt][2] = NEGV;
            if ((wr1 >> (sh + 1)) & 1) sc[nt][3] = NEGV;
        }

        float t0 = sc[0][0], t1 = sc[0][2];
#pragma unroll
        for (int nt = 0; nt < 8; nt++) {
            t0 = fmaxf(t0, fmaxf(sc[nt][0], sc[nt][1]));
            t1 = fmaxf(t1, fmaxf(sc[nt][2], sc[nt][3]));
        }
        t0 = fmaxf(t0, __shfl_xor_sync(0xffffffffu, t0, 1));
        t0 = fmaxf(t0, __shfl_xor_sync(0xffffffffu, t0, 2));
        t1 = fmaxf(t1, __shfl_xor_sync(0xffffffffu, t1, 1));
        t1 = fmaxf(t1, __shfl_xor_sync(0xffffffffu, t1, 2));
        float nm0 = fmaxf(m0, t0), nm1 = fmaxf(m1, t1);
        float al0 = __expf(m0 - nm0), al1 = __expf(m1 - nm1);
        m0 = nm0; m1 = nm1;

        uint32_t pa[4][4];
        float ps0 = 0.f, ps1 = 0.f;
#pragma unroll
        for (int nt = 0; nt < 8; nt++) {
            float p00 = __expf(sc[nt][0] - nm0);
            float p01 = __expf(sc[nt][1] - nm0);
            float p10 = __expf(sc[nt][2] - nm1);
            float p11 = __expf(sc[nt][3] - nm1);
            ps0 += p00 + p01;
            ps1 += p10 + p11;
            int tt = nt >> 1;
            int hi = (nt & 1) ? 2 : 0;
            pa[tt][hi + 0] = pack_f16x2(p00, p01);
            pa[tt][hi + 1] = pack_f16x2(p10, p11);
        }
        ps0 += __shfl_xor_sync(0xffffffffu, ps0, 1);
        ps0 += __shfl_xor_sync(0xffffffffu, ps0, 2);
        ps1 += __shfl_xor_sync(0xffffffffu, ps1, 1);
        ps1 += __shfl_xor_sync(0xffffffffu, ps1, 2);
        l0 = l0 * al0 + ps0;
        l1 = l1 * al1 + ps1;

#pragma unroll
        for (int nd = 0; nd < 8; nd++) {
            o[nd][0] *= al0; o[nd][1] *= al0;
            o[nd][2] *= al1; o[nd][3] *= al1;
        }
#pragma unroll
        for (int nd = 0; nd < 8; nd++) {
            uint32_t bv[8];
            uint32_t base = vs_base + nd * 16;
            ldsm_x4_t(bv,     base);
            ldsm_x4_t(bv + 4, base + 32 * KVP * 2);
            mma_f16(o[nd], pa[0], bv);
            mma_f16(o[nd], pa[1], bv + 2);
            mma_f16(o[nd], pa[2], bv + 4);
            mma_f16(o[nd], pa[3], bv + 6);
        }
        __syncthreads();
        cur = (cur == 2) ? 0 : cur + 1;
    }

    float i0 = 1.f / l0, i1 = 1.f / l1;
    size_t r0 = (size_t)(b * SEQ + qb + gid);
#pragma unroll
    for (int nd = 0; nd < 8; nd++) {
        int c = h * DK + nd * 8 + 2 * ctid;
        uint32_t p0 = pack_f16x2(o[nd][0] * i0, o[nd][1] * i0);
        uint32_t p1 = pack_f16x2(o[nd][2] * i1, o[nd][3] * i1);
        *(uint32_t*)(Ctx + r0 * DMODEL + c)       = p0;
        *(uint32_t*)(Ctx + (r0 + 8) * DMODEL + c) = p1;
    }
}

// ---------------------------------------------------------------------------
// Launch
// ---------------------------------------------------------------------------
extern "C" void kernel_launch(void* const* d_in, const int* in_sizes, int n_in,
                              void* d_out, int out_size)
{
    const float* x    = (const float*)d_in[0];
    const int*   mask = (const int*)d_in[1];
    const float* Wq   = (const float*)d_in[2];
    const float* bq   = (const float*)d_in[3];
    const float* Wk   = (const float*)d_in[4];
    const float* bk   = (const float*)d_in[5];
    const float* Wv   = (const float*)d_in[6];
    const float* bv   = (const float*)d_in[7];
    const float* Wo   = (const float*)d_in[8];
    const float* bo   = (const float*)d_in[9];
    float* out = (float*)d_out;

    __half *Xh, *Wh, *P, *Ch; uint32_t* Mb;
    cudaGetSymbolAddress((void**)&Xh, g_Xh);
    cudaGetSymbolAddress((void**)&Wh, g_Wh);
    cudaGetSymbolAddress((void**)&P,  g_P);
    cudaGetSymbolAddress((void**)&Ch, g_Ch);
    cudaGetSymbolAddress((void**)&Mb, g_Mb);

    cudaFuncSetAttribute((const void*)gemm_f16_t<__half>,
                         cudaFuncAttributeMaxDynamicSharedMemorySize, GSMEM);
    cudaFuncSetAttribute((const void*)gemm_f16_t<float>,
                         cudaFuncAttributeMaxDynamicSharedMemorySize, GSMEM);

    pack_mask<<<BATCH * SEQ * MW / 8, 256>>>(mask, Mb);

    const int NX = MTOT * DMODEL / 4;
    const int NW = DMODEL * DMODEL / 4;
    cvt_f16<<<NX / 256, 256>>>(x,  Xh, NX);
    cvt_f16<<<NW / 256, 256>>>(Wq, Wh + 0 * DMODEL * DMODEL, NW);
    cvt_f16<<<NW / 256, 256>>>(Wk, Wh + 1 * DMODEL * DMODEL, NW);
    cvt_f16<<<NW / 256, 256>>>(Wv, Wh + 2 * DMODEL * DMODEL, NW);
    cvt_f16<<<NW / 256, 256>>>(Wo, Wh + 3 * DMODEL * DMODEL, NW);

    // Batched QKV: one launch, 768 CTAs of 256x128 tiles.
    dim3 gq(DMODEL / TBN, MTOT / TBM, 3);   // (8, 32, 3)
    gemm_f16_t<__half><<<gq, 256, GSMEM>>>(Xh, Wh, bq, bk, bv, P, 0.125f);

    __half* Qh = P;
    __half* Kh = P + (size_t)1 * MTOT * DMODEL;
    __half* Vh = P + (size_t)2 * MTOT * DMODEL;

    dim3 fg(SEQ / 128, NHEADS, BATCH);      // (16, 16, 4)
    flash_f16<<<fg, 256>>>(Qh, Kh, Vh, Mb, Ch);

    // Output projection
    dim3 go(DMODEL / TBN, MTOT / TBM, 1);   // (8, 32, 1)
    gemm_f16_t<float><<<go, 256, GSMEM>>>(Ch, Wh + 3 * DMODEL * DMODEL, bo, bo, bo, out, 1.0f);
}

// round 17
// speedup vs baseline: 1.0631x; 1.0631x over previous
#include <cuda_runtime.h>
#include <cuda_fp16.h>
#include <cstdint>
#include <math.h>

#define BATCH 4
#define SEQ   2048
#define DMODEL 1024
#define NHEADS 16
#define DK    64
#define MTOT  (BATCH*SEQ)      // 8192
#define NEGV  (-1e9f)
#define MW    (SEQ/32)         // 64 mask words per row

// Scratch (alloc-free rule: __device__ globals).
__device__ __half   g_Xh[MTOT * DMODEL];       // x in fp16
__device__ __half   g_Wh[4 * DMODEL * DMODEL]; // Wq,Wk,Wv,Wo in fp16
__device__ __half   g_P [3 * MTOT * DMODEL];   // Q(scaled)|K|V slices
__device__ __half   g_Ch[MTOT * DMODEL];       // ctx in fp16
__device__ uint32_t g_Mb[BATCH * SEQ * MW];    // bit-packed mask (2 MB)

__device__ __forceinline__ uint32_t pack_f16x2(float lo, float hi) {
    uint32_t r;
    asm("cvt.rn.f16x2.f32 %0, %1, %2;" : "=r"(r) : "f"(hi), "f"(lo));
    return r;
}

__device__ __forceinline__ uint32_t sptr(const void* p) {
    return (uint32_t)__cvta_generic_to_shared(p);
}

__device__ __forceinline__ void cp_async16(uint32_t smem, const void* g) {
    asm volatile("cp.async.cg.shared.global [%0], [%1], 16;" :: "r"(smem), "l"(g));
}
#define CP_COMMIT() asm volatile("cp.async.commit_group;")
#define CP_WAIT(N)  asm volatile("cp.async.wait_group %0;" :: "n"(N))

__device__ __forceinline__ void ldsm_x4(uint32_t* r, uint32_t addr) {
    asm volatile("ldmatrix.sync.aligned.m8n8.x4.shared.b16 {%0,%1,%2,%3}, [%4];"
                 : "=r"(r[0]), "=r"(r[1]), "=r"(r[2]), "=r"(r[3]) : "r"(addr));
}

__device__ __forceinline__ void ldsm_x4_t(uint32_t* r, uint32_t addr) {
    asm volatile("ldmatrix.sync.aligned.m8n8.x4.trans.shared.b16 {%0,%1,%2,%3}, [%4];"
                 : "=r"(r[0]), "=r"(r[1]), "=r"(r[2]), "=r"(r[3]) : "r"(addr));
}

__device__ __forceinline__ void mma_f16(float* c, const uint32_t* a, const uint32_t* b) {
    asm volatile(
        "mma.sync.aligned.m16n8k16.row.col.f32.f16.f16.f32 "
        "{%0,%1,%2,%3}, {%4,%5,%6,%7}, {%8,%9}, {%0,%1,%2,%3};"
        : "+f"(c[0]), "+f"(c[1]), "+f"(c[2]), "+f"(c[3])
        : "r"(a[0]), "r"(a[1]), "r"(a[2]), "r"(a[3]), "r"(b[0]), "r"(b[1]));
}

// ---------------------------------------------------------------------------
// Merged fp32 -> fp16 convert: x (2M float4) then 4 weights (256K each).
// ---------------------------------------------------------------------------
#define NXF4 (MTOT * DMODEL / 4)        // 2097152
#define NWF4 (DMODEL * DMODEL / 4)      // 262144
#define NALLF4 (NXF4 + 4 * NWF4)        // 3145728

__global__ __launch_bounds__(256) void cvt_all(
    const float* __restrict__ x,
    const float* __restrict__ w0, const float* __restrict__ w1,
    const float* __restrict__ w2, const float* __restrict__ w3,
    __half* __restrict__ xh, __half* __restrict__ wh)
{
    int i = blockIdx.x * 256 + threadIdx.x;
    if (i >= NALLF4) return;
    const float* src; __half* dst; int off;
    if (i < NXF4) {
        src = x; dst = xh; off = i;
    } else {
        int j = i - NXF4;
        int r = j / NWF4;                // weight index 0..3
        off = j - r * NWF4;
        src = (r == 0) ? w0 : (r == 1) ? w1 : (r == 2) ? w2 : w3;
        dst = wh + (size_t)r * DMODEL * DMODEL;
    }
    float4 v = *(const float4*)(src + (size_t)off * 4);
    uint2 o;
    o.x = pack_f16x2(v.x, v.y);
    o.y = pack_f16x2(v.z, v.w);
    *(uint2*)(dst + (size_t)off * 4) = o;
}

// ---------------------------------------------------------------------------
// Bit-pack the int32 mask
// ---------------------------------------------------------------------------
__global__ __launch_bounds__(256) void pack_mask(const int* __restrict__ mask,
                                                 uint32_t* __restrict__ mb)
{
    int w    = blockIdx.x * 8 + (threadIdx.x >> 5);
    int lane = threadIdx.x & 31;
    int v    = mask[(size_t)w * 32 + lane];
    uint32_t bits = __ballot_sync(0xffffffffu, v != 0);
    if (lane == 0) mb[w] = bits;
}

// ---------------------------------------------------------------------------
// fp16 GEMM (R15, verified): 3-stage cp.async, z-batched weights.
// Block 128x128, K-tile 64, 256 threads (8 warps: 4M x 2N).
// ---------------------------------------------------------------------------
#define TBM 128
#define TBN 128
#define TBK 64
#define AP  72
#define BP  136
#define NKT (DMODEL / TBK)   // 16
#define STG 3
#define ASZH (TBM * AP)
#define BSZH (TBK * BP)
#define ASZB (ASZH * 2)
#define BSZB (BSZH * 2)
#define GSMEM (STG * (ASZB + BSZB))  // 107520 B

template <typename OutT>
__global__ __launch_bounds__(256, 2) void gemm_f16_t(
    const __half* __restrict__ A, const __half* __restrict__ Wbase,
    const float* __restrict__ b0, const float* __restrict__ b1,
    const float* __restrict__ b2, OutT* __restrict__ Ybase, float s0)
{
    extern __shared__ __half dsm[];
    __half* Asm = dsm;
    __half* Bsm = dsm + STG * ASZH;

    const int tid  = threadIdx.x;
    const int wid  = tid >> 5;
    const int lane = tid & 31;
    const int gid  = lane >> 2;
    const int ctid = lane & 3;
    const int wm   = wid & 3;
    const int wn   = wid >> 2;

    const int z  = blockIdx.z;
    const __half* W = Wbase + (size_t)z * DMODEL * DMODEL;
    OutT* Y = Ybase + (size_t)z * MTOT * DMODEL;
    const float* bias = (z == 0) ? b0 : (z == 1) ? b1 : b2;
    const float oscale = (z == 0) ? s0 : 1.0f;

    const int bm = blockIdx.y * TBM;
    const int bn = blockIdx.x * TBN;

    float acc[2][8][4];
#pragma unroll
    for (int i = 0; i < 2; i++)
#pragma unroll
        for (int j = 0; j < 8; j++)
#pragma unroll
            for (int t = 0; t < 4; t++) acc[i][j][t] = 0.f;

    int ar[4], ac[4], br[4], bc[4];
    uint32_t asw[4], bsw[4];
#pragma unroll
    for (int i = 0; i < 4; i++) {
        int f = i * 256 + tid;
        ar[i] = f >> 3;  ac[i] = (f & 7) * 8;
        br[i] = f >> 4;  bc[i] = (f & 15) * 8;
        asw[i] = sptr(&Asm[ar[i] * AP + ac[i]]);
        bsw[i] = sptr(&Bsm[br[i] * BP + bc[i]]);
    }

    const uint32_t a_base0 = sptr(&Asm[(wm * 32 + (lane & 15)) * AP + (lane >> 4) * 8]);
    const uint32_t b_base0 = sptr(&Bsm[((lane & 7) + (lane >> 3) * 8) * BP + wn * 64]);

#pragma unroll
    for (int s = 0; s < 2; s++) {
        const int k0 = s * TBK;
#pragma unroll
        for (int i = 0; i < 4; i++) {
            cp_async16(asw[i] + s * ASZB, A + (size_t)(bm + ar[i]) * DMODEL + k0 + ac[i]);
            cp_async16(bsw[i] + s * BSZB, W + (size_t)(k0 + br[i]) * DMODEL + bn + bc[i]);
        }
        CP_COMMIT();
    }

    int cur = 0;
    for (int kt = 0; kt < NKT; kt++) {
        if (kt + 2 < NKT) {
            const int nst = (cur == 0) ? 2 : cur - 1;
            const int k0  = (kt + 2) * TBK;
#pragma unroll
            for (int i = 0; i < 4; i++) {
                cp_async16(asw[i] + nst * ASZB, A + (size_t)(bm + ar[i]) * DMODEL + k0 + ac[i]);
                cp_async16(bsw[i] + nst * BSZB, W + (size_t)(k0 + br[i]) * DMODEL + bn + bc[i]);
            }
            CP_COMMIT();
            CP_WAIT(2);
        } else if (kt + 1 < NKT) {
            CP_WAIT(1);
        } else {
            CP_WAIT(0);
        }
        __syncthreads();

        const uint32_t a_base = a_base0 + cur * ASZB;
        const uint32_t b_base = b_base0 + cur * BSZB;
#pragma unroll
        for (int kh = 0; kh < 2; kh++) {
            uint32_t a[2][2][4];
#pragma unroll
            for (int mt = 0; mt < 2; mt++)
#pragma unroll
                for (int ks = 0; ks < 2; ks++)
                    ldsm_x4(a[mt][ks], a_base + mt * 16 * AP * 2 + (kh * 2 + ks) * 32);
#pragma unroll
            for (int nt = 0; nt < 8; nt++) {
                uint32_t bb[4];
                ldsm_x4_t(bb, b_base + kh * 32 * BP * 2 + nt * 16);
                mma_f16(acc[0][nt], a[0][0], bb);
                mma_f16(acc[0][nt], a[0][1], bb + 2);
                mma_f16(acc[1][nt], a[1][0], bb);
                mma_f16(acc[1][nt], a[1][1], bb + 2);
            }
        }
        __syncthreads();
        cur = (cur == 2) ? 0 : cur + 1;
    }

#pragma unroll
    for (int nt = 0; nt < 8; nt++) {
        int c = bn + wn * 64 + nt * 8 + ctid * 2;
        float bb0 = __ldg(bias + c);
        float bb1 = __ldg(bias + c + 1);
#pragma unroll
        for (int mt = 0; mt < 2; mt++) {
            int r0 = bm + wm * 32 + mt * 16 + gid;
            float v00 = (acc[mt][nt][0] + bb0) * oscale;
            float v01 = (acc[mt][nt][1] + bb1) * oscale;
            float v10 = (acc[mt][nt][2] + bb0) * oscale;
            float v11 = (acc[mt][nt][3] + bb1) * oscale;
            if constexpr (sizeof(OutT) == 4) {
                float2 p0 = make_float2(v00, v01);
                float2 p1 = make_float2(v10, v11);
                *(float2*)((float*)Y + (size_t)r0 * DMODEL + c)       = p0;
                *(float2*)((float*)Y + (size_t)(r0 + 8) * DMODEL + c) = p1;
            } else {
                uint32_t p0 = pack_f16x2(v00, v01);
                uint32_t p1 = pack_f16x2(v10, v11);
                *(uint32_t*)((__half*)Y + (size_t)r0 * DMODEL + c)       = p0;
                *(uint32_t*)((__half*)Y + (size_t)(r0 + 8) * DMODEL + c) = p1;
            }
        }
    }
}

// ---------------------------------------------------------------------------
// Flash attention: fp16 mma.sync, 4-stage cp.async, TWO key-tiles per
// iteration (one barrier pair per 128 keys). Dynamic smem 73.7 KB.
// 256 threads; 128 queries/block; key tile 64.
// ---------------------------------------------------------------------------
#define FKT 64
#define KVP 72
#define NFT (SEQ / FKT)        // 32
#define NPAIR (NFT / 2)        // 16
#define KVSZB (FKT * KVP * 2)  // 9216 B per stage
#define FSTG 4
#define FSMEM (FSTG * 2 * KVSZB)  // 73728 B (K stages then V stages)

__global__ __launch_bounds__(256, 2) void flash_f16(
    const __half* __restrict__ Qh, const __half* __restrict__ Kh,
    const __half* __restrict__ Vh, const uint32_t* __restrict__ mbits,
    __half* __restrict__ Ctx)
{
    extern __shared__ __align__(16) __half fsm[];
    __half* Ksm = fsm;                    // 4 stages
    __half* Vsm = fsm + FSTG * FKT * KVP; // 4 stages

    const int tid  = threadIdx.x;
    const int w    = tid >> 5;
    const int lane = tid & 31;
    const int gid  = lane >> 2;
    const int ctid = lane & 3;

    const int h  = blockIdx.y;
    const int b  = blockIdx.z;
    const int qb = blockIdx.x * 128 + w * 16;

    uint32_t qa[4][4];
    {
        const __half* q0 = Qh + (size_t)(b * SEQ + qb + gid    ) * DMODEL + h * DK;
        const __half* q1 = Qh + (size_t)(b * SEQ + qb + gid + 8) * DMODEL + h * DK;
#pragma unroll
        for (int t = 0; t < 4; t++) {
            qa[t][0] = *(const uint32_t*)(q0 + 16 * t + 2 * ctid);
            qa[t][1] = *(const uint32_t*)(q1 + 16 * t + 2 * ctid);
            qa[t][2] = *(const uint32_t*)(q0 + 16 * t + 2 * ctid + 8);
            qa[t][3] = *(const uint32_t*)(q1 + 16 * t + 2 * ctid + 8);
        }
    }

    float m0 = -INFINITY, m1 = -INFINITY, l0 = 0.f, l1 = 0.f;
    float o[8][4];
#pragma unroll
    for (int nd = 0; nd < 8; nd++)
#pragma unroll
        for (int t = 0; t < 4; t++) o[nd][t] = 0.f;

    const uint32_t* mb0 = mbits + ((size_t)(b * SEQ) + qb + gid) * MW;
    const uint32_t* mb1 = mb0 + 8 * MW;

    int kr[2], kc[2];
    uint32_t ksw[2], vsw[2];
#pragma unroll
    for (int i = 0; i < 2; i++) {
        int f = i * 256 + tid;
        kr[i] = f >> 3;  kc[i] = (f & 7) * 8;
        ksw[i] = sptr(&Ksm[kr[i] * KVP + kc[i]]);
        vsw[i] = sptr(&Vsm[kr[i] * KVP + kc[i]]);
    }

    const uint32_t ks_base0 = sptr(&Ksm[(lane & 7) * KVP + (lane >> 3) * 8]);
    const uint32_t vs_base0 = sptr(&Vsm[((lane & 7) + (lane >> 3) * 8) * KVP]);

    // prologue: prefetch pair 0 (tiles 0,1 -> stages 0,1) as ONE group
#pragma unroll
    for (int t = 0; t < 2; t++)
#pragma unroll
        for (int i = 0; i < 2; i++) {
            size_t ga = (size_t)(b * SEQ + t * FKT + kr[i]) * DMODEL + h * DK + kc[i];
            cp_async16(ksw[i] + t * KVSZB, Kh + ga);
            cp_async16(vsw[i] + t * KVSZB, Vh + ga);
        }
    CP_COMMIT();

    for (int pj = 0; pj < NPAIR; pj++) {
        const int pbase = (pj & 1) * 2;          // stages of this pair: pbase, pbase+1
        // prefetch pair pj+1 into the other pair's stages (freed by trailing sync)
        if (pj + 1 < NPAIR) {
            const int nbase = ((pj + 1) & 1) * 2;
            const int kt0   = (pj + 1) * 2 * FKT;
#pragma unroll
            for (int t = 0; t < 2; t++)
#pragma unroll
                for (int i = 0; i < 2; i++) {
                    size_t ga = (size_t)(b * SEQ + kt0 + t * FKT + kr[i]) * DMODEL + h * DK + kc[i];
                    cp_async16(ksw[i] + (nbase + t) * KVSZB, Kh + ga);
                    cp_async16(vsw[i] + (nbase + t) * KVSZB, Vh + ga);
                }
            CP_COMMIT();
            CP_WAIT(1);
        } else {
            CP_WAIT(0);
        }
        __syncthreads();

        // ---- compute both tiles of this pair ----
#pragma unroll
        for (int tt2 = 0; tt2 < 2; tt2++) {
            const int kt = (pj * 2 + tt2) * FKT;
            const uint32_t ks_base = ks_base0 + (pbase + tt2) * KVSZB;
            const uint32_t vs_base = vs_base0 + (pbase + tt2) * KVSZB;

            uint2 w0 = *(const uint2*)(mb0 + (kt >> 5));
            uint2 w1 = *(const uint2*)(mb1 + (kt >> 5));

            float sc[8][4];
#pragma unroll
            for (int nt = 0; nt < 8; nt++) {
#pragma unroll
                for (int t4 = 0; t4 < 4; t4++) sc[nt][t4] = 0.f;
                uint32_t bk[8];
                uint32_t base = ks_base + nt * 8 * KVP * 2;
                ldsm_x4(bk,     base);
                ldsm_x4(bk + 4, base + 64);
                mma_f16(sc[nt], qa[0], bk);
                mma_f16(sc[nt], qa[1], bk + 2);
                mma_f16(sc[nt], qa[2], bk + 4);
                mma_f16(sc[nt], qa[3], bk + 6);
            }

#pragma unroll
            for (int nt = 0; nt < 8; nt++) {
                int kl = nt * 8 + 2 * ctid;
                uint32_t wr0 = (kl & 32) ? w0.y : w0.x;
                uint32_t wr1 = (kl & 32) ? w1.y : w1.x;
                int sh = kl & 31;
                if ((wr0 >> sh) & 1)       sc[nt][0] = NEGV;
                if ((wr0 >> (sh + 1)) & 1) sc[nt][1] = NEGV;
                if ((wr1 >> sh) & 1)       sc[nt][2] = NEGV;
                if ((wr1 >> (sh + 1)) & 1) sc[nt][3] = NEGV;
            }

            float t0 = sc[0][0], t1 = sc[0][2];
#pragma unroll
            for (int nt = 0; nt < 8; nt++) {
                t0 = fmaxf(t0, fmaxf(sc[nt][0], sc[nt][1]));
                t1 = fmaxf(t1, fmaxf(sc[nt][2], sc[nt][3]));
            }
            t0 = fmaxf(t0, __shfl_xor_sync(0xffffffffu, t0, 1));
            t0 = fmaxf(t0, __shfl_xor_sync(0xffffffffu, t0, 2));
            t1 = fmaxf(t1, __shfl_xor_sync(0xffffffffu, t1, 1));
            t1 = fmaxf(t1, __shfl_xor_sync(0xffffffffu, t1, 2));
            float nm0 = fmaxf(m0, t0), nm1 = fmaxf(m1, t1);
            float al0 = __expf(m0 - nm0), al1 = __expf(m1 - nm1);
            m0 = nm0; m1 = nm1;

            uint32_t pa[4][4];
            float ps0 = 0.f, ps1 = 0.f;
#pragma unroll
            for (int nt = 0; nt < 8; nt++) {
                float p00 = __expf(sc[nt][0] - nm0);
                float p01 = __expf(sc[nt][1] - nm0);
                float p10 = __expf(sc[nt][2] - nm1);
                float p11 = __expf(sc[nt][3] - nm1);
                ps0 += p00 + p01;
                ps1 += p10 + p11;
                int tt = nt >> 1;
                int hi = (nt & 1) ? 2 : 0;
                pa[tt][hi + 0] = pack_f16x2(p00, p01);
                pa[tt][hi + 1] = pack_f16x2(p10, p11);
            }
            ps0 += __shfl_xor_sync(0xffffffffu, ps0, 1);
            ps0 += __shfl_xor_sync(0xffffffffu, ps0, 2);
            ps1 += __shfl_xor_sync(0xffffffffu, ps1, 1);
            ps1 += __shfl_xor_sync(0xffffffffu, ps1, 2);
            l0 = l0 * al0 + ps0;
            l1 = l1 * al1 + ps1;

#pragma unroll
            for (int nd = 0; nd < 8; nd++) {
                o[nd][0] *= al0; o[nd][1] *= al0;
                o[nd][2] *= al1; o[nd][3] *= al1;
            }
#pragma unroll
            for (int nd = 0; nd < 8; nd++) {
                uint32_t bv[8];
                uint32_t base = vs_base + nd * 16;
                ldsm_x4_t(bv,     base);
                ldsm_x4_t(bv + 4, base + 32 * KVP * 2);
                mma_f16(o[nd], pa[0], bv);
                mma_f16(o[nd], pa[1], bv + 2);
                mma_f16(o[nd], pa[2], bv + 4);
                mma_f16(o[nd], pa[3], bv + 6);
            }
        }
        __syncthreads();
    }

    float i0 = 1.f / l0, i1 = 1.f / l1;
    size_t r0 = (size_t)(b * SEQ + qb + gid);
#pragma unroll
    for (int nd = 0; nd < 8; nd++) {
        int c = h * DK + nd * 8 + 2 * ctid;
        uint32_t p0 = pack_f16x2(o[nd][0] * i0, o[nd][1] * i0);
        uint32_t p1 = pack_f16x2(o[nd][2] * i1, o[nd][3] * i1);
        *(uint32_t*)(Ctx + r0 * DMODEL + c)       = p0;
        *(uint32_t*)(Ctx + (r0 + 8) * DMODEL + c) = p1;
    }
}

// ---------------------------------------------------------------------------
// Launch
// ---------------------------------------------------------------------------
extern "C" void kernel_launch(void* const* d_in, const int* in_sizes, int n_in,
                              void* d_out, int out_size)
{
    const float* x    = (const float*)d_in[0];
    const int*   mask = (const int*)d_in[1];
    const float* Wq   = (const float*)d_in[2];
    const float* bq   = (const float*)d_in[3];
    const float* Wk   = (const float*)d_in[4];
    const float* bk   = (const float*)d_in[5];
    const float* Wv   = (const float*)d_in[6];
    const float* bv   = (const float*)d_in[7];
    const float* Wo   = (const float*)d_in[8];
    const float* bo   = (const float*)d_in[9];
    float* out = (float*)d_out;

    __half *Xh, *Wh, *P, *Ch; uint32_t* Mb;
    cudaGetSymbolAddress((void**)&Xh, g_Xh);
    cudaGetSymbolAddress((void**)&Wh, g_Wh);
    cudaGetSymbolAddress((void**)&P,  g_P);
    cudaGetSymbolAddress((void**)&Ch, g_Ch);
    cudaGetSymbolAddress((void**)&Mb, g_Mb);

    cudaFuncSetAttribute((const void*)gemm_f16_t<__half>,
                         cudaFuncAttributeMaxDynamicSharedMemorySize, GSMEM);
    cudaFuncSetAttribute((const void*)gemm_f16_t<float>,
                         cudaFuncAttributeMaxDynamicSharedMemorySize, GSMEM);
    cudaFuncSetAttribute((const void*)flash_f16,
                         cudaFuncAttributeMaxDynamicSharedMemorySize, FSMEM);

    pack_mask<<<BATCH * SEQ * MW / 8, 256>>>(mask, Mb);
    cvt_all<<<(NALLF4 + 255) / 256, 256>>>(x, Wq, Wk, Wv, Wo, Xh, Wh);

    // Batched QKV: one launch, 1536 CTAs of 128x128 tiles.
    dim3 gq(DMODEL / TBN, MTOT / TBM, 3);   // (8, 64, 3)
    gemm_f16_t<__half><<<gq, 256, GSMEM>>>(Xh, Wh, bq, bk, bv, P, 0.125f);

    __half* Qh = P;
    __half* Kh = P + (size_t)1 * MTOT * DMODEL;
    __half* Vh = P + (size_t)2 * MTOT * DMODEL;

    dim3 fg(SEQ / 128, NHEADS, BATCH);      // (16, 16, 4)
    flash_f16<<<fg, 256, FSMEM>>>(Qh, Kh, Vh, Mb, Ch);

    // Output projection
    dim3 go(DMODEL / TBN, MTOT / TBM, 1);   // (8, 64, 1)
    gemm_f16_t<float><<<go, 256, GSMEM>>>(Ch, Wh + 3 * DMODEL * DMODEL, bo, bo, bo, out, 1.0f);
}